// round 13
// baseline (speedup 1.0000x reference)
#include <cuda_runtime.h>
#include <cuda_bf16.h>
#include <cstdint>

// B=8, L=4000, D=512, WINDOW=5.
// Identity: shift/unshift cancel -> per column c, sort consecutive 5-row
// windows whose start rows are ≡ c (mod 5), circular over L.
//
// R13: R12 ring kernel, but BOTH input reads and output writes use
// L2::evict_last. Footprint v+out = 131MB vs 126MB L2: keeping both
// resident leaves only ~5MB of overflow thrash, cutting steady-state DRAM
// traffic from ~87MB to ~10-20MB per replay. (R12 evidence: bench improved
// with L2 hints while cold-cache ncu profile stayed flat -> the win lives
// in cross-replay L2 residency.)

#define LROWS 4000
#define DCOLS 512
#define ROWBYTES (DCOLS * 4)        // 2048
#define TROWS 10
#define RING 40
#define NTILES (LROWS / TROWS)      // 400 per batch
#define GPB 37                      // CTAs per batch: 37*8 = 296 = one wave
#define NTHREADS 512
#define SMEM_BYTES (RING * ROWBYTES + 64)   // ring + 4 mbarriers

#define CE(x, y) { float _lo = fminf(x, y); float _hi = fmaxf(x, y); x = _lo; y = _hi; }

// Load rows [first, first+n) (unwrapped coords) into ring rows (r mod 40),
// one 2KB bulk copy per row, with evict_last policy. tx0 only.
__device__ __forceinline__ void load_rows(const float* vb, int first, int n,
                                          uint32_t ring_base, uint32_t mbar,
                                          uint64_t pol_last)
{
    asm volatile("mbarrier.arrive.expect_tx.shared.b64 _, [%0], %1;"
                 :: "r"(mbar), "r"((uint32_t)(n * ROWBYTES)) : "memory");
    for (int r = first; r < first + n; r++) {
        int gs = r; if (gs < 0) gs += LROWS; else if (gs >= LROWS) gs -= LROWS;
        int rr = r % RING; if (rr < 0) rr += RING;
        asm volatile(
            "cp.async.bulk.shared::cta.global.mbarrier::complete_tx::bytes"
            ".L2::cache_hint [%0], [%1], %2, [%3], %4;"
            :: "r"(ring_base + (uint32_t)(rr * ROWBYTES)),
               "l"((const char*)(vb + (size_t)gs * DCOLS)),
               "r"((uint32_t)ROWBYTES), "r"(mbar), "l"(pol_last) : "memory");
    }
}

__device__ __forceinline__ void mbar_wait(uint32_t mbar, uint32_t phase)
{
    uint32_t done;
    asm volatile(
        "{\n\t.reg .pred p;\n\t"
        "mbarrier.try_wait.parity.acquire.cta.shared::cta.b64 p, [%1], %2;\n\t"
        "selp.b32 %0, 1, 0, p;\n\t}"
        : "=r"(done) : "r"(mbar), "r"(phase) : "memory");
    if (!done) {
        asm volatile(
            "{\n\t.reg .pred P1;\n\t"
            "WL_%=:\n\t"
            "mbarrier.try_wait.parity.acquire.cta.shared::cta.b64 P1, [%0], %1, 0x989680;\n\t"
            "@P1 bra.uni WD_%=;\n\t"
            "bra.uni WL_%=;\n\t"
            "WD_%=:\n\t}"
            :: "r"(mbar), "r"(phase) : "memory");
    }
}

// Sort the 5-row window starting at unwrapped row s, column tx, in the ring.
__device__ __forceinline__ void sort_win(float* sm, int s, int tx)
{
    int r0 = s % RING; if (r0 < 0) r0 += RING;
    int r1 = r0 + 1; if (r1 >= RING) r1 -= RING;
    int r2 = r1 + 1; if (r2 >= RING) r2 -= RING;
    int r3 = r2 + 1; if (r3 >= RING) r3 -= RING;
    int r4 = r3 + 1; if (r4 >= RING) r4 -= RING;
    float a0 = sm[r0 * DCOLS + tx];
    float a1 = sm[r1 * DCOLS + tx];
    float a2 = sm[r2 * DCOLS + tx];
    float a3 = sm[r3 * DCOLS + tx];
    float a4 = sm[r4 * DCOLS + tx];
    CE(a0, a1); CE(a3, a4); CE(a2, a4);
    CE(a2, a3); CE(a0, a3); CE(a0, a2);
    CE(a1, a4); CE(a1, a3); CE(a1, a2);
    sm[r0 * DCOLS + tx] = a0;
    sm[r1 * DCOLS + tx] = a1;
    sm[r2 * DCOLS + tx] = a2;
    sm[r3 * DCOLS + tx] = a3;
    sm[r4 * DCOLS + tx] = a4;
}

__global__ __launch_bounds__(NTHREADS, 2)
void swd_ring_kernel(const float* __restrict__ v, float* __restrict__ out) {
    extern __shared__ float sm[];
    uint32_t smem_base;
    asm("{ .reg .u64 t; cvta.to.shared.u64 t, %1; cvt.u32.u64 %0, t; }"
        : "=r"(smem_base) : "l"(sm));
    const uint32_t mbb = smem_base + RING * ROWBYTES;   // 4 mbarriers

    const int tx = threadIdx.x;                 // column 0..511
    const int g  = blockIdx.x;                  // chunk within batch
    const int b  = blockIdx.y;                  // batch

    const int t0 = (g * NTILES) / GPB;          // first tile (inclusive)
    const int t1 = ((g + 1) * NTILES) / GPB;    // last tile (exclusive)
    const int n  = t1 - t0;                     // 10 or 11
    const int P0 = t0 * TROWS;

    const float* __restrict__ vb = v   + (size_t)b * LROWS * DCOLS;
    float*       __restrict__ ob = out + (size_t)b * LROWS * DCOLS;

    // L2 policy: keep BOTH input and output resident (evict_last).
    uint64_t pol_last;
    asm volatile("createpolicy.fractional.L2::evict_last.b64 %0, 1.0;"
                 : "=l"(pol_last));

    if (tx == 0) {
        #pragma unroll
        for (int j = 0; j < 4; j++)
            asm volatile("mbarrier.init.shared.b64 [%0], 1;"
                         :: "r"(mbb + 8u * j) : "memory");
    }
    __syncthreads();

    // Prime: full 19-row frame for tile 0; 10 new rows for tile 1.
    if (tx == 0) {
        load_rows(vb, P0 - 4, 19, smem_base, mbb + 0, pol_last);
        if (n > 1) load_rows(vb, P0 + 15, 10, smem_base, mbb + 8, pol_last);
    }

    const int o = (tx + 4) % 5;                 // per-column window phase

    for (int i = 0; i < n; i++) {
        const int P = P0 + i * TROWS;
        mbar_wait(mbb + 8u * (i & 3), (i >> 2) & 1);

        // First tile of the chunk also sorts the lower straddling window;
        // steady tiles inherit it (already sorted by the previous tile).
        if (i == 0) sort_win(sm, P - 4 + o, tx);
        sort_win(sm, P + 1 + o, tx);
        sort_win(sm, P + 6 + o, tx);
        __syncthreads();

        if (tx == 0) {
            asm volatile("fence.proxy.async.shared::cta;" ::: "memory");
            asm volatile(
                "cp.async.bulk.global.shared::cta.bulk_group"
                ".L2::cache_hint [%0], [%1], %2, %3;"
                :: "l"((char*)(ob + (size_t)P * DCOLS)),
                   "r"(smem_base + (uint32_t)((P % RING) * ROWBYTES)),
                   "r"((uint32_t)(TROWS * ROWBYTES)), "l"(pol_last)
                : "memory");
            asm volatile("cp.async.bulk.commit_group;" ::: "memory");
            if (i + 2 < n) {
                // Store i-1 must drain before its ring rows are overwritten.
                asm volatile("cp.async.bulk.wait_group 1;" ::: "memory");
                load_rows(vb, P + 25, 10, smem_base,
                          mbb + 8u * ((i + 2) & 3), pol_last);
            }
        }
    }

    if (tx == 0) {
        asm volatile("cp.async.bulk.wait_group 0;" ::: "memory");
    }
}

extern "C" void kernel_launch(void* const* d_in, const int* in_sizes, int n_in,
                              void* d_out, int out_size) {
    const float* v = (const float*)d_in[2];   // inputs: q (unused), k (unused), v
    float* out     = (float*)d_out;

    cudaFuncSetAttribute(swd_ring_kernel,
                         cudaFuncAttributeMaxDynamicSharedMemorySize, SMEM_BYTES);

    dim3 grid(GPB, 8);                        // 37 x 8 = 296 CTAs = one wave
    swd_ring_kernel<<<grid, NTHREADS, SMEM_BYTES>>>(v, out);
}

// round 14
// speedup vs baseline: 1.1928x; 1.1928x over previous
#include <cuda_runtime.h>
#include <cuda_bf16.h>
#include <cstdint>

// B=8, L=4000, D=512, WINDOW=5.
// Identity: shift/unshift cancel -> per column c, sort consecutive 5-row
// windows whose start rows are ≡ c (mod 5), circular over L.
//
// R14: best-known L2 policy (R12: input evict_last, output evict_first —
// R13 proved all-evict_last thrashes) + deeper decoupled pipeline.
// RING=48 (98.3KB, 2 CTAs/SM) grows ring-reuse distance to ~4.8 tiles, so
// the load for tile i+2 is issued at the TOP of iteration i, gated only by
// "store i-2 drained" (wait_group 1) — no longer serialized behind store i's
// commit and store i-1's DRAM drain. Loads are per-row (2KB) so ring-edge
// wrap is natural; the 10-row output store splits at the ring edge.

#define LROWS 4000
#define DCOLS 512
#define ROWBYTES (DCOLS * 4)        // 2048
#define TROWS 10
#define RING 48
#define NTILES (LROWS / TROWS)      // 400 per batch
#define GPB 37                      // 37*8 = 296 CTAs = one wave
#define NTHREADS 512
#define SMEM_BYTES (RING * ROWBYTES + 64)

#define CE(x, y) { float _lo = fminf(x, y); float _hi = fmaxf(x, y); x = _lo; y = _hi; }

__device__ __forceinline__ void load_rows(const float* vb, int first, int n,
                                          uint32_t ring_base, uint32_t mbar,
                                          uint64_t pol_last)
{
    asm volatile("mbarrier.arrive.expect_tx.shared.b64 _, [%0], %1;"
                 :: "r"(mbar), "r"((uint32_t)(n * ROWBYTES)) : "memory");
    for (int r = first; r < first + n; r++) {
        int gs = r; if (gs < 0) gs += LROWS; else if (gs >= LROWS) gs -= LROWS;
        int rr = r % RING; if (rr < 0) rr += RING;
        asm volatile(
            "cp.async.bulk.shared::cta.global.mbarrier::complete_tx::bytes"
            ".L2::cache_hint [%0], [%1], %2, [%3], %4;"
            :: "r"(ring_base + (uint32_t)(rr * ROWBYTES)),
               "l"((const char*)(vb + (size_t)gs * DCOLS)),
               "r"((uint32_t)ROWBYTES), "r"(mbar), "l"(pol_last) : "memory");
    }
}

__device__ __forceinline__ void mbar_wait(uint32_t mbar, uint32_t phase)
{
    uint32_t done;
    asm volatile(
        "{\n\t.reg .pred p;\n\t"
        "mbarrier.try_wait.parity.acquire.cta.shared::cta.b64 p, [%1], %2;\n\t"
        "selp.b32 %0, 1, 0, p;\n\t}"
        : "=r"(done) : "r"(mbar), "r"(phase) : "memory");
    if (!done) {
        asm volatile(
            "{\n\t.reg .pred P1;\n\t"
            "WL_%=:\n\t"
            "mbarrier.try_wait.parity.acquire.cta.shared::cta.b64 P1, [%0], %1, 0x989680;\n\t"
            "@P1 bra.uni WD_%=;\n\t"
            "bra.uni WL_%=;\n\t"
            "WD_%=:\n\t}"
            :: "r"(mbar), "r"(phase) : "memory");
    }
}

__device__ __forceinline__ void sort_win(float* sm, int s, int tx)
{
    int r0 = s % RING; if (r0 < 0) r0 += RING;
    int r1 = r0 + 1; if (r1 >= RING) r1 -= RING;
    int r2 = r1 + 1; if (r2 >= RING) r2 -= RING;
    int r3 = r2 + 1; if (r3 >= RING) r3 -= RING;
    int r4 = r3 + 1; if (r4 >= RING) r4 -= RING;
    float a0 = sm[r0 * DCOLS + tx];
    float a1 = sm[r1 * DCOLS + tx];
    float a2 = sm[r2 * DCOLS + tx];
    float a3 = sm[r3 * DCOLS + tx];
    float a4 = sm[r4 * DCOLS + tx];
    CE(a0, a1); CE(a3, a4); CE(a2, a4);
    CE(a2, a3); CE(a0, a3); CE(a0, a2);
    CE(a1, a4); CE(a1, a3); CE(a1, a2);
    sm[r0 * DCOLS + tx] = a0;
    sm[r1 * DCOLS + tx] = a1;
    sm[r2 * DCOLS + tx] = a2;
    sm[r3 * DCOLS + tx] = a3;
    sm[r4 * DCOLS + tx] = a4;
}

__global__ __launch_bounds__(NTHREADS, 2)
void swd_ring_kernel(const float* __restrict__ v, float* __restrict__ out) {
    extern __shared__ float sm[];
    uint32_t smem_base;
    asm("{ .reg .u64 t; cvta.to.shared.u64 t, %1; cvt.u32.u64 %0, t; }"
        : "=r"(smem_base) : "l"(sm));
    const uint32_t mbb = smem_base + RING * ROWBYTES;

    const int tx = threadIdx.x;
    const int g  = blockIdx.x;
    const int b  = blockIdx.y;

    const int t0 = (g * NTILES) / GPB;
    const int t1 = ((g + 1) * NTILES) / GPB;
    const int n  = t1 - t0;                     // 10 or 11
    const int P0 = t0 * TROWS;

    const float* __restrict__ vb = v   + (size_t)b * LROWS * DCOLS;
    float*       __restrict__ ob = out + (size_t)b * LROWS * DCOLS;

    uint64_t pol_last, pol_first;
    asm volatile("createpolicy.fractional.L2::evict_last.b64 %0, 1.0;"
                 : "=l"(pol_last));
    asm volatile("createpolicy.fractional.L2::evict_first.b64 %0, 1.0;"
                 : "=l"(pol_first));

    if (tx == 0) {
        #pragma unroll
        for (int j = 0; j < 4; j++)
            asm volatile("mbarrier.init.shared.b64 [%0], 1;"
                         :: "r"(mbb + 8u * j) : "memory");
    }
    __syncthreads();

    if (tx == 0) {
        load_rows(vb, P0 - 4, 19, smem_base, mbb + 0, pol_last);
        if (n > 1) load_rows(vb, P0 + 15, 10, smem_base, mbb + 8, pol_last);
    }

    const int o = (tx + 4) % 5;

    for (int i = 0; i < n; i++) {
        const int P = P0 + i * TROWS;
        mbar_wait(mbb + 8u * (i & 3), (i >> 2) & 1);

        // Early load issue for tile i+2: its ring rows (≡ P-23..P-14 mod 48)
        // belong to stores i-3/i-2; wait_group 1 guarantees both drained
        // (at most store i-1 outstanding).
        if (tx == 0 && i + 2 < n) {
            asm volatile("cp.async.bulk.wait_group 1;" ::: "memory");
            load_rows(vb, P + 25, 10, smem_base,
                      mbb + 8u * ((i + 2) & 3), pol_last);
        }

        if (i == 0) sort_win(sm, P - 4 + o, tx);
        sort_win(sm, P + 1 + o, tx);
        sort_win(sm, P + 6 + o, tx);
        __syncthreads();

        if (tx == 0) {
            asm volatile("fence.proxy.async.shared::cta;" ::: "memory");
            int rr = P % RING;                       // 0..47
            int n1 = RING - rr; if (n1 > TROWS) n1 = TROWS;  // rows before edge
            asm volatile(
                "cp.async.bulk.global.shared::cta.bulk_group"
                ".L2::cache_hint [%0], [%1], %2, %3;"
                :: "l"((char*)(ob + (size_t)P * DCOLS)),
                   "r"(smem_base + (uint32_t)(rr * ROWBYTES)),
                   "r"((uint32_t)(n1 * ROWBYTES)), "l"(pol_first)
                : "memory");
            if (n1 < TROWS) {                        // wrapped tail from row 0
                asm volatile(
                    "cp.async.bulk.global.shared::cta.bulk_group"
                    ".L2::cache_hint [%0], [%1], %2, %3;"
                    :: "l"((char*)(ob + (size_t)(P + n1) * DCOLS)),
                       "r"(smem_base),
                       "r"((uint32_t)((TROWS - n1) * ROWBYTES)), "l"(pol_first)
                    : "memory");
            }
            asm volatile("cp.async.bulk.commit_group;" ::: "memory");
        }
    }

    if (tx == 0) {
        asm volatile("cp.async.bulk.wait_group 0;" ::: "memory");
    }
}

extern "C" void kernel_launch(void* const* d_in, const int* in_sizes, int n_in,
                              void* d_out, int out_size) {
    const float* v = (const float*)d_in[2];   // inputs: q (unused), k (unused), v
    float* out     = (float*)d_out;

    cudaFuncSetAttribute(swd_ring_kernel,
                         cudaFuncAttributeMaxDynamicSharedMemorySize, SMEM_BYTES);

    dim3 grid(GPB, 8);                        // 296 CTAs = one wave
    swd_ring_kernel<<<grid, NTHREADS, SMEM_BYTES>>>(v, out);
}